// round 3
// baseline (speedup 1.0000x reference)
#include <cuda_runtime.h>
#include <math.h>

#define BATCH 4096
#define HID   1024
#define STEPS 16
#define KTILES (HID / 16)

// ---------------- device scratch (no allocations allowed) ----------------
// W4 layout: [sel][ (g*HID + j)*HID + k ], g in {0:r,1:z,2:in,3:hn}
//   sel 0: steps >= 2 (x == h):  r/z slabs = W_ih+W_hh, in = W_ih_n, hn = W_hh_n
//   sel 1: step 1     (x == 0):  r/z slabs = W_hh only, in = 0,      hn = W_hh_n
__device__ __align__(16) float g_W4[2][4 * HID * HID];
__device__ __align__(16) float g_b4[4 * HID];
__device__ __align__(16) float g_h[2][BATCH * HID];

// ---------------- packed f32x2 helpers ----------------
union F2U { float2 f; unsigned long long u; };

__device__ __forceinline__ unsigned long long lds2(const float* p) {
    F2U t; t.f = *(const float2*)p; return t.u;
}
__device__ __forceinline__ float2 unpack2(unsigned long long v) {
    F2U t; t.u = v; return t.f;
}

#if defined(__CUDA_ARCH__) && (__CUDA_ARCH__ >= 1000)
#define FMA2(c, a, b) asm("fma.rn.f32x2 %0, %1, %2, %0;" : "+l"(c) : "l"(a), "l"(b))
#else
// numerically identical scalar fallback (2x FFMA)
#define FMA2(c, a, b) do {                                        \
    F2U _c, _a, _b; _c.u = (c); _a.u = (a); _b.u = (b);           \
    _c.f.x = fmaf(_a.f.x, _b.f.x, _c.f.x);                        \
    _c.f.y = fmaf(_a.f.y, _b.f.y, _c.f.y);                        \
    (c) = _c.u;                                                   \
} while (0)
#endif

__device__ __forceinline__ float sigf(float x) {
    return 1.0f / (1.0f + __expf(-x));
}
__device__ __forceinline__ float tanh_fast(float x) {
    // 1 - 2/(exp(2x)+1): EX2+RCP path, ~2ulp, saturates correctly at +-inf
    float e = __expf(2.0f * x);
    return 1.0f - 2.0f / (e + 1.0f);
}

// ---------------- weight folding ----------------
__global__ void prep_kernel(const float* __restrict__ W_ih, const float* __restrict__ W_hh,
                            const float* __restrict__ b_ih, const float* __restrict__ b_hh) {
    int idx = blockIdx.x * 256 + threadIdx.x;
    if (idx >= 4 * HID * HID) return;
    int k = idx & (HID - 1);
    int j = (idx >> 10) & (HID - 1);
    int g = idx >> 20;

    float w, ws1;
    if (g == 0) {
        float a = W_ih[j * HID + k], b = W_hh[j * HID + k];
        w = a + b; ws1 = b;
    } else if (g == 1) {
        int r = HID + j;
        float a = W_ih[r * HID + k], b = W_hh[r * HID + k];
        w = a + b; ws1 = b;
    } else if (g == 2) {
        int r = 2 * HID + j;
        w = W_ih[r * HID + k]; ws1 = 0.0f;
    } else {
        int r = 2 * HID + j;
        w = W_hh[r * HID + k]; ws1 = w;
    }
    g_W4[0][idx] = w;
    g_W4[1][idx] = ws1;

    if (k == 0) {
        float bb;
        if (g == 0)      bb = b_ih[j] + b_hh[j];
        else if (g == 1) bb = b_ih[HID + j] + b_hh[HID + j];
        else if (g == 2) bb = b_ih[2 * HID + j];
        else             bb = b_hh[2 * HID + j];
        g_b4[g * HID + j] = bb;
    }
}

// ---------------- fused gate GEMM + GRU pointwise ----------------
// CTA tile: 128 batch rows x 32 hidden cols x 4 gate slabs.
// Thread tile: 8 rows x 8 cols, accumulated as 4 row-pairs x 8 cols in f32x2.
// grid = (HID/32, BATCH/128)
__global__ __launch_bounds__(256, 2)
void gate_gemm(const float* __restrict__ extA, int useExt, int wsel, int srcbuf, int dstbuf) {
    const float* __restrict__ A = useExt ? extA : g_h[srcbuf];
    const float* __restrict__ hold = A;  // h_old == GEMM input (x == h)
    const float* __restrict__ W = g_W4[wsel];
    float* __restrict__ Hn = g_h[dstbuf];

    __shared__ __align__(16) float As[16][128];       // k-major: As[k][m]
    __shared__ __align__(16) float Bsd[4][16][64];    // duplicated: [g][k][2j],[2j+1]

    int tid = threadIdx.x;
    int tx = tid & 15, ty = tid >> 4;
    int ty4 = ty * 4;
    int rowbase = blockIdx.y * 128;
    int jbase   = blockIdx.x * 32;

    int lr = tid >> 1;        // 0..127
    int lk = (tid & 1) * 8;   // 0 or 8
    int bg = lr >> 5, bj = lr & 31;
    const float* Aptr = A + (size_t)(rowbase + lr) * HID + lk;
    const float* Wptr = W + (size_t)(bg * HID + jbase + bj) * HID + lk;

    unsigned long long acc[4][8];
#pragma unroll
    for (int r = 0; r < 4; ++r)
#pragma unroll
        for (int c = 0; c < 8; ++c) acc[r][c] = 0ull;

    float4 pa0 = *(const float4*)(Aptr);
    float4 pa1 = *(const float4*)(Aptr + 4);
    float4 pb0 = *(const float4*)(Wptr);
    float4 pb1 = *(const float4*)(Wptr + 4);

    for (int kt = 0; kt < KTILES; ++kt) {
        __syncthreads();
        As[lk + 0][lr] = pa0.x; As[lk + 1][lr] = pa0.y;
        As[lk + 2][lr] = pa0.z; As[lk + 3][lr] = pa0.w;
        As[lk + 4][lr] = pa1.x; As[lk + 5][lr] = pa1.y;
        As[lk + 6][lr] = pa1.z; As[lk + 7][lr] = pa1.w;
        *(float2*)&Bsd[bg][lk + 0][2 * bj] = make_float2(pb0.x, pb0.x);
        *(float2*)&Bsd[bg][lk + 1][2 * bj] = make_float2(pb0.y, pb0.y);
        *(float2*)&Bsd[bg][lk + 2][2 * bj] = make_float2(pb0.z, pb0.z);
        *(float2*)&Bsd[bg][lk + 3][2 * bj] = make_float2(pb0.w, pb0.w);
        *(float2*)&Bsd[bg][lk + 4][2 * bj] = make_float2(pb1.x, pb1.x);
        *(float2*)&Bsd[bg][lk + 5][2 * bj] = make_float2(pb1.y, pb1.y);
        *(float2*)&Bsd[bg][lk + 6][2 * bj] = make_float2(pb1.z, pb1.z);
        *(float2*)&Bsd[bg][lk + 7][2 * bj] = make_float2(pb1.w, pb1.w);
        __syncthreads();

        if (kt + 1 < KTILES) {
            const float* ap = Aptr + (kt + 1) * 16;
            const float* wp = Wptr + (kt + 1) * 16;
            pa0 = *(const float4*)(ap);
            pa1 = *(const float4*)(ap + 4);
            pb0 = *(const float4*)(wp);
            pb1 = *(const float4*)(wp + 4);
        }

#pragma unroll
        for (int kk = 0; kk < 16; ++kk) {
            unsigned long long a01 = lds2(&As[kk][ty4]);
            unsigned long long a23 = lds2(&As[kk][ty4 + 2]);
            unsigned long long a45 = lds2(&As[kk][ty4 + 64]);
            unsigned long long a67 = lds2(&As[kk][ty4 + 66]);
            unsigned long long b[8];
#pragma unroll
            for (int g = 0; g < 4; ++g) {
                b[2 * g]     = lds2(&Bsd[g][kk][4 * tx]);
                b[2 * g + 1] = lds2(&Bsd[g][kk][4 * tx + 2]);
            }
#pragma unroll
            for (int c = 0; c < 8; ++c) {
                FMA2(acc[0][c], a01, b[c]);
                FMA2(acc[1][c], a23, b[c]);
                FMA2(acc[2][c], a45, b[c]);
                FMA2(acc[3][c], a67, b[c]);
            }
        }
    }

    // Fused GRU pointwise epilogue: acc[rp][2g+q] -> h_new for rows (m0, m0+1), col j.
#pragma unroll
    for (int q = 0; q < 2; ++q) {
        int j = jbase + 2 * tx + q;
        float br  = g_b4[0 * HID + j];
        float bz  = g_b4[1 * HID + j];
        float bin = g_b4[2 * HID + j];
        float bhn = g_b4[3 * HID + j];
#pragma unroll
        for (int rp = 0; rp < 4; ++rp) {
            int m0 = rowbase + (rp < 2 ? ty4 + 2 * rp : 64 + ty4 + 2 * (rp - 2));
            float2 vr = unpack2(acc[rp][0 + q]);
            float2 vz = unpack2(acc[rp][2 + q]);
            float2 vi = unpack2(acc[rp][4 + q]);
            float2 vh = unpack2(acc[rp][6 + q]);

            float r0 = sigf(vr.x + br);
            float z0 = sigf(vz.x + bz);
            float n0 = tanh_fast(vi.x + bin + r0 * (vh.x + bhn));
            float hp0 = hold[(size_t)m0 * HID + j];
            Hn[(size_t)m0 * HID + j] = (1.0f - z0) * n0 + z0 * hp0;

            float r1 = sigf(vr.y + br);
            float z1 = sigf(vz.y + bz);
            float n1 = tanh_fast(vi.y + bin + r1 * (vh.y + bhn));
            float hp1 = hold[(size_t)(m0 + 1) * HID + j];
            Hn[(size_t)(m0 + 1) * HID + j] = (1.0f - z1) * n1 + z1 * hp1;
        }
    }
}

// ---------------- output projection: out = relu(h) @ W_out^T + b_out ----------------
// grid = (1024/128, BATCH/128); same f32x2 scheme, relu fused on A-tile store.
__global__ __launch_bounds__(256, 2)
void out_gemm(int srcbuf, const float* __restrict__ Wout, const float* __restrict__ bout,
              float* __restrict__ out) {
    const float* __restrict__ A = g_h[srcbuf];

    __shared__ __align__(16) float As[16][128];    // k-major, relu'd
    __shared__ __align__(16) float Bsd[16][256];   // duplicated: [k][2c],[2c+1]

    int tid = threadIdx.x;
    int tx = tid & 15, ty = tid >> 4;
    int ty4 = ty * 4;
    int rowbase = blockIdx.y * 128;
    int colbase = blockIdx.x * 128;

    int lr = tid >> 1;
    int lk = (tid & 1) * 8;
    const float* Aptr = A + (size_t)(rowbase + lr) * HID + lk;
    const float* Wptr = Wout + (size_t)(colbase + lr) * HID + lk;

    unsigned long long acc[4][8];
#pragma unroll
    for (int r = 0; r < 4; ++r)
#pragma unroll
        for (int c = 0; c < 8; ++c) acc[r][c] = 0ull;

    float4 pa0 = *(const float4*)(Aptr);
    float4 pa1 = *(const float4*)(Aptr + 4);
    float4 pb0 = *(const float4*)(Wptr);
    float4 pb1 = *(const float4*)(Wptr + 4);

    for (int kt = 0; kt < KTILES; ++kt) {
        __syncthreads();
        As[lk + 0][lr] = fmaxf(pa0.x, 0.0f); As[lk + 1][lr] = fmaxf(pa0.y, 0.0f);
        As[lk + 2][lr] = fmaxf(pa0.z, 0.0f); As[lk + 3][lr] = fmaxf(pa0.w, 0.0f);
        As[lk + 4][lr] = fmaxf(pa1.x, 0.0f); As[lk + 5][lr] = fmaxf(pa1.y, 0.0f);
        As[lk + 6][lr] = fmaxf(pa1.z, 0.0f); As[lk + 7][lr] = fmaxf(pa1.w, 0.0f);
        *(float2*)&Bsd[lk + 0][2 * lr] = make_float2(pb0.x, pb0.x);
        *(float2*)&Bsd[lk + 1][2 * lr] = make_float2(pb0.y, pb0.y);
        *(float2*)&Bsd[lk + 2][2 * lr] = make_float2(pb0.z, pb0.z);
        *(float2*)&Bsd[lk + 3][2 * lr] = make_float2(pb0.w, pb0.w);
        *(float2*)&Bsd[lk + 4][2 * lr] = make_float2(pb1.x, pb1.x);
        *(float2*)&Bsd[lk + 5][2 * lr] = make_float2(pb1.y, pb1.y);
        *(float2*)&Bsd[lk + 6][2 * lr] = make_float2(pb1.z, pb1.z);
        *(float2*)&Bsd[lk + 7][2 * lr] = make_float2(pb1.w, pb1.w);
        __syncthreads();

        if (kt + 1 < KTILES) {
            const float* ap = Aptr + (kt + 1) * 16;
            const float* wp = Wptr + (kt + 1) * 16;
            pa0 = *(const float4*)(ap);
            pa1 = *(const float4*)(ap + 4);
            pb0 = *(const float4*)(wp);
            pb1 = *(const float4*)(wp + 4);
        }

#pragma unroll
        for (int kk = 0; kk < 16; ++kk) {
            unsigned long long a01 = lds2(&As[kk][ty4]);
            unsigned long long a23 = lds2(&As[kk][ty4 + 2]);
            unsigned long long a45 = lds2(&As[kk][ty4 + 64]);
            unsigned long long a67 = lds2(&As[kk][ty4 + 66]);
            unsigned long long b[8];
#pragma unroll
            for (int c = 0; c < 8; ++c)
                b[c] = lds2(&Bsd[kk][2 * (tx + 16 * c)]);
#pragma unroll
            for (int c = 0; c < 8; ++c) {
                FMA2(acc[0][c], a01, b[c]);
                FMA2(acc[1][c], a23, b[c]);
                FMA2(acc[2][c], a45, b[c]);
                FMA2(acc[3][c], a67, b[c]);
            }
        }
    }

#pragma unroll
    for (int c = 0; c < 8; ++c) {
        int col = colbase + tx + 16 * c;
        float bb = bout[col];
#pragma unroll
        for (int rp = 0; rp < 4; ++rp) {
            int m0 = rowbase + (rp < 2 ? ty4 + 2 * rp : 64 + ty4 + 2 * (rp - 2));
            float2 v = unpack2(acc[rp][c]);
            out[(size_t)m0 * 1024 + col]       = v.x + bb;
            out[(size_t)(m0 + 1) * 1024 + col] = v.y + bb;
        }
    }
}

// ---------------- launch ----------------
extern "C" void kernel_launch(void* const* d_in, const int* in_sizes, int n_in,
                              void* d_out, int out_size) {
    const float* hidden = (const float*)d_in[0];  // (1, 4096, 1024)
    const float* W_ih   = (const float*)d_in[1];  // (3072, 1024)
    const float* W_hh   = (const float*)d_in[2];  // (3072, 1024)
    const float* b_ih   = (const float*)d_in[3];
    const float* b_hh   = (const float*)d_in[4];
    const float* W_out  = (const float*)d_in[5];  // (1024, 1024)
    const float* b_out  = (const float*)d_in[6];
    float* out = (float*)d_out;                    // (16, 4096, 1024)

    prep_kernel<<<(4 * HID * HID) / 256, 256>>>(W_ih, W_hh, b_ih, b_hh);

    dim3 ggrid(HID / 32, BATCH / 128);   // 32 x 32
    dim3 ogrid(1024 / 128, BATCH / 128); // 8 x 32

    for (int t = 0; t < STEPS; ++t) {
        int useExt = (t == 0) ? 1 : 0;
        int wsel   = (t == 0) ? 1 : 0;
        int srcbuf = (t == 0) ? 0 : ((t + 1) & 1);
        int dstbuf = t & 1;
        gate_gemm<<<ggrid, 256>>>(hidden, useExt, wsel, srcbuf, dstbuf);
        out_gemm<<<ogrid, 256>>>(dstbuf, W_out, b_out,
                                 out + (size_t)t * BATCH * 1024);
    }
}

// round 7
// speedup vs baseline: 2.5041x; 2.5041x over previous
#include <cuda_runtime.h>
#include <cuda_bf16.h>
#include <stdint.h>
#include <math.h>

#define BATCH 4096
#define HID   1024
#define STEPS 16
#define BK    64
#define NCH   (HID / BK)   // 16 k-chunks

// stage layout: 4 subtiles of 128 rows x 64 bf16 (128B rows, swizzled)
#define ST_AHI 0
#define ST_ALO 16384
#define ST_BHI 32768
#define ST_BLO 49152
#define ST_SZ  65536
#define SMEM_TOTAL (2 * ST_SZ)   // 131072

// ---------------- device scratch (no allocations) ----------------
// Folded gate weights bf16-split. Rows: (g*HID + j) x K, g in {r,z,in,hn}
//   sel 0: steps >= 1 (x==h): r/z = W_ih+W_hh, in = W_ih_n, hn = W_hh_n
//   sel 1: step 0    (x==0):  r/z = W_hh,      in = 0,      hn = W_hh_n
__device__ __align__(16) __nv_bfloat16 g_Whi[2][4 * HID * HID];
__device__ __align__(16) __nv_bfloat16 g_Wlo[2][4 * HID * HID];
__device__ __align__(16) __nv_bfloat16 g_WOhi[HID * HID];
__device__ __align__(16) __nv_bfloat16 g_WOlo[HID * HID];
__device__ __align__(16) __nv_bfloat16 g_hhi[2][BATCH * HID];
__device__ __align__(16) __nv_bfloat16 g_hlo[2][BATCH * HID];
__device__ __align__(16) __nv_bfloat16 g_rhi[BATCH * HID];
__device__ __align__(16) __nv_bfloat16 g_rlo[BATCH * HID];
__device__ __align__(16) float g_b4[4 * HID];

// ---------------- helpers ----------------
__device__ __forceinline__ uint32_t smem_u32(const void* p) {
    uint32_t a;
    asm("{ .reg .u64 t; cvta.to.shared.u64 t, %1; cvt.u32.u64 %0, t; }" : "=r"(a) : "l"(p));
    return a;
}
__device__ __forceinline__ void cp16(uint32_t s, const void* g) {
    asm volatile("cp.async.cg.shared.global [%0], [%1], 16;" :: "r"(s), "l"(g));
}
#define CP_COMMIT() asm volatile("cp.async.commit_group;" ::: "memory")
#define CP_WAIT1()  asm volatile("cp.async.wait_group 1;" ::: "memory")
#define CP_WAIT0()  asm volatile("cp.async.wait_group 0;" ::: "memory")

#define LDSM4(d, addr) \
    asm volatile("ldmatrix.sync.aligned.m8n8.x4.shared.b16 {%0,%1,%2,%3}, [%4];" \
        : "=r"((d)[0]), "=r"((d)[1]), "=r"((d)[2]), "=r"((d)[3]) : "r"(addr))
#define LDSM2(d0, d1, addr) \
    asm volatile("ldmatrix.sync.aligned.m8n8.x2.shared.b16 {%0,%1}, [%2];" \
        : "=r"(d0), "=r"(d1) : "r"(addr))
#define MMA(c, a, b0, b1) \
    asm volatile("mma.sync.aligned.m16n8k16.row.col.f32.bf16.bf16.f32 " \
        "{%0,%1,%2,%3}, {%4,%5,%6,%7}, {%8,%9}, {%0,%1,%2,%3};" \
        : "+f"((c)[0]), "+f"((c)[1]), "+f"((c)[2]), "+f"((c)[3]) \
        : "r"((a)[0]), "r"((a)[1]), "r"((a)[2]), "r"((a)[3]), "r"(b0), "r"(b1))

__device__ __forceinline__ float sigf(float x) { return 1.0f / (1.0f + __expf(-x)); }
__device__ __forceinline__ float tanh_fast(float x) {
    float e = __expf(2.0f * x);
    return 1.0f - 2.0f / (e + 1.0f);
}
__device__ __forceinline__ void split_bf16(float v, __nv_bfloat16& hi, __nv_bfloat16& lo) {
    hi = __float2bfloat16(v);
    lo = __float2bfloat16(v - __bfloat162float(hi));
}
__device__ __forceinline__ uint32_t pack2(__nv_bfloat16 a, __nv_bfloat16 b) {
    __nv_bfloat162 t; t.x = a; t.y = b; return *(uint32_t*)&t;
}

// ---------------- prep kernels ----------------
__global__ void prep_fold(const float* __restrict__ W_ih, const float* __restrict__ W_hh,
                          const float* __restrict__ b_ih, const float* __restrict__ b_hh) {
    int idx = blockIdx.x * 256 + threadIdx.x;
    if (idx >= 4 * HID * HID) return;
    int k = idx & (HID - 1);
    int j = (idx >> 10) & (HID - 1);
    int g = idx >> 20;

    float w, ws1;
    if (g == 0) {
        float a = W_ih[j * HID + k], b = W_hh[j * HID + k];
        w = a + b; ws1 = b;
    } else if (g == 1) {
        int r = HID + j;
        float a = W_ih[r * HID + k], b = W_hh[r * HID + k];
        w = a + b; ws1 = b;
    } else if (g == 2) {
        int r = 2 * HID + j;
        w = W_ih[r * HID + k]; ws1 = 0.0f;
    } else {
        int r = 2 * HID + j;
        w = W_hh[r * HID + k]; ws1 = w;
    }
    __nv_bfloat16 hi, lo;
    split_bf16(w, hi, lo);   g_Whi[0][idx] = hi; g_Wlo[0][idx] = lo;
    split_bf16(ws1, hi, lo); g_Whi[1][idx] = hi; g_Wlo[1][idx] = lo;

    if (k == 0) {
        float bb;
        if (g == 0)      bb = b_ih[j] + b_hh[j];
        else if (g == 1) bb = b_ih[HID + j] + b_hh[HID + j];
        else if (g == 2) bb = b_ih[2 * HID + j];
        else             bb = b_hh[2 * HID + j];
        g_b4[g * HID + j] = bb;
    }
}

__global__ void prep_wout(const float* __restrict__ W_out) {
    int idx = blockIdx.x * 256 + threadIdx.x;
    if (idx >= HID * HID) return;
    __nv_bfloat16 hi, lo;
    split_bf16(W_out[idx], hi, lo);
    g_WOhi[idx] = hi; g_WOlo[idx] = lo;
}

__global__ void prep_h(const float* __restrict__ hidden) {
    int idx = blockIdx.x * 256 + threadIdx.x;
    if (idx >= BATCH * HID) return;
    __nv_bfloat16 hi, lo;
    split_bf16(hidden[idx], hi, lo);
    g_hhi[0][idx] = hi; g_hlo[0][idx] = lo;
}

// ---------------- gate GEMM + GRU pointwise ----------------
// grid (32, 32): bx = 32-j tile, by = 128-row batch tile. CTA N = 4 gates x 32 j.
__global__ __launch_bounds__(256, 1)
void gate_mma(int wsel, int src, int dst) {
    extern __shared__ char smem[];
    uint32_t sb = smem_u32(smem);
    int tid = threadIdx.x;
    int lane = tid & 31, wid = tid >> 5;
    int wm = wid >> 2, wn = wid & 3;        // warp grid 2 x 4; wn == gate
    int rowbase = blockIdx.y * 128;
    int jbase   = blockIdx.x * 32;

    const __nv_bfloat16* Ahi = g_hhi[src];
    const __nv_bfloat16* Alo = g_hlo[src];
    const __nv_bfloat16* Whi = g_Whi[wsel];
    const __nv_bfloat16* Wlo = g_Wlo[wsel];

    // loader mapping: 2 threads per row, 4 chunks each
    int r = tid >> 1;
    int cp0 = (tid & 1) * 4;
    size_t aoff = (size_t)(rowbase + r) * HID;
    size_t boff = (size_t)((r >> 5) * HID + jbase + (r & 31)) * HID;

    float acc[4][4][4];
#pragma unroll
    for (int a = 0; a < 4; ++a)
#pragma unroll
        for (int b = 0; b < 4; ++b)
#pragma unroll
            for (int c = 0; c < 4; ++c) acc[a][b][c] = 0.0f;

#pragma unroll
    for (int s = 0; s < 2; ++s) {
        int k0 = s * BK;
        uint32_t st = sb + s * ST_SZ;
#pragma unroll
        for (int i = 0; i < 4; ++i) {
            int c = cp0 + i;
            uint32_t so = (uint32_t)(r * 128 + ((c ^ (r & 7)) << 4));
            cp16(st + ST_AHI + so, Ahi + aoff + k0 + c * 8);
            cp16(st + ST_ALO + so, Alo + aoff + k0 + c * 8);
            cp16(st + ST_BHI + so, Whi + boff + k0 + c * 8);
            cp16(st + ST_BLO + so, Wlo + boff + k0 + c * 8);
        }
        CP_COMMIT();
    }

    int a_row = wm * 64 + (lane & 15);
    int a_chi = lane >> 4;
    int b_row = wn * 32 + (lane & 7);
    int b_chi = (lane >> 3) & 1;

    for (int cc = 0; cc < NCH; ++cc) {
        int s = cc & 1;
        if (cc == NCH - 1) CP_WAIT0(); else CP_WAIT1();
        __syncthreads();
        uint32_t st = sb + s * ST_SZ;

#pragma unroll
        for (int kk = 0; kk < 4; ++kk) {
            uint32_t Ah[4][4], Al[4][4];
#pragma unroll
            for (int mf = 0; mf < 4; ++mf) {
                int row = a_row + mf * 16;
                uint32_t so = (uint32_t)(row * 128 + (((2 * kk + a_chi) ^ (row & 7)) << 4));
                LDSM4(Ah[mf], st + ST_AHI + so);
                LDSM4(Al[mf], st + ST_ALO + so);
            }
#pragma unroll
            for (int nf = 0; nf < 4; ++nf) {
                int row = b_row + nf * 8;
                uint32_t so = (uint32_t)(row * 128 + (((2 * kk + b_chi) ^ (row & 7)) << 4));
                uint32_t bh0, bh1, bl0, bl1;
                LDSM2(bh0, bh1, st + ST_BHI + so);
                LDSM2(bl0, bl1, st + ST_BLO + so);
#pragma unroll
                for (int mf = 0; mf < 4; ++mf) {
                    MMA(acc[mf][nf], Ah[mf], bh0, bh1);
                    MMA(acc[mf][nf], Ah[mf], bl0, bl1);
                    MMA(acc[mf][nf], Al[mf], bh0, bh1);
                }
            }
        }
        __syncthreads();
        if (cc + 2 < NCH) {
            int k0 = (cc + 2) * BK;
            uint32_t st2 = sb + s * ST_SZ;
#pragma unroll
            for (int i = 0; i < 4; ++i) {
                int c = cp0 + i;
                uint32_t so = (uint32_t)(r * 128 + ((c ^ (r & 7)) << 4));
                cp16(st2 + ST_AHI + so, Ahi + aoff + k0 + c * 8);
                cp16(st2 + ST_ALO + so, Alo + aoff + k0 + c * 8);
                cp16(st2 + ST_BHI + so, Whi + boff + k0 + c * 8);
                cp16(st2 + ST_BLO + so, Wlo + boff + k0 + c * 8);
            }
            CP_COMMIT();
        } else {
            CP_COMMIT();  // keep group accounting uniform
        }
    }

    // ---- exchange accs through smem: Cs[128][132] ----
    __syncthreads();
    float* Cs = (float*)smem;
#pragma unroll
    for (int mf = 0; mf < 4; ++mf)
#pragma unroll
        for (int nf = 0; nf < 4; ++nf) {
            int m = wm * 64 + mf * 16 + (lane >> 2);
            int n = wn * 32 + nf * 8 + (lane & 3) * 2;
            Cs[m * 132 + n]           = acc[mf][nf][0];
            Cs[m * 132 + n + 1]       = acc[mf][nf][1];
            Cs[(m + 8) * 132 + n]     = acc[mf][nf][2];
            Cs[(m + 8) * 132 + n + 1] = acc[mf][nf][3];
        }
    __syncthreads();

    // ---- GRU pointwise: thread -> row m=tid/2, 16 j values ----
    {
        int m = tid >> 1;
        int j0l = (tid & 1) * 16;
        int mg = rowbase + m;
        int j0 = jbase + j0l;
        size_t hoff = (size_t)mg * HID + j0;

        __nv_bfloat16 hhb[16], hlb[16];
        *(uint4*)&hhb[0] = *(const uint4*)(g_hhi[src] + hoff);
        *(uint4*)&hhb[8] = *(const uint4*)(g_hhi[src] + hoff + 8);
        *(uint4*)&hlb[0] = *(const uint4*)(g_hlo[src] + hoff);
        *(uint4*)&hlb[8] = *(const uint4*)(g_hlo[src] + hoff + 8);

        uint32_t ohh[8], ohl[8], orh[8], orl[8];
#pragma unroll
        for (int p = 0; p < 8; ++p) {
            __nv_bfloat16 ehh[2], ehl[2], erh[2], erl[2];
#pragma unroll
            for (int u = 0; u < 2; ++u) {
                int i = 2 * p + u;
                int jl = j0l + i;
                int j = j0 + i;
                float vr = Cs[m * 132 + 0 * 32 + jl] + g_b4[j];
                float vz = Cs[m * 132 + 1 * 32 + jl] + g_b4[HID + j];
                float vi = Cs[m * 132 + 2 * 32 + jl] + g_b4[2 * HID + j];
                float vh = Cs[m * 132 + 3 * 32 + jl] + g_b4[3 * HID + j];
                float rg = sigf(vr);
                float zz = sigf(vz);
                float nn = tanh_fast(vi + rg * vh);
                float hp = __bfloat162float(hhb[i]) + __bfloat162float(hlb[i]);
                float hn = (1.0f - zz) * nn + zz * hp;
                split_bf16(hn, ehh[u], ehl[u]);
                split_bf16(fmaxf(hn, 0.0f), erh[u], erl[u]);
            }
            ohh[p] = pack2(ehh[0], ehh[1]);
            ohl[p] = pack2(ehl[0], ehl[1]);
            orh[p] = pack2(erh[0], erh[1]);
            orl[p] = pack2(erl[0], erl[1]);
        }
        *(uint4*)(g_hhi[dst] + hoff)     = make_uint4(ohh[0], ohh[1], ohh[2], ohh[3]);
        *(uint4*)(g_hhi[dst] + hoff + 8) = make_uint4(ohh[4], ohh[5], ohh[6], ohh[7]);
        *(uint4*)(g_hlo[dst] + hoff)     = make_uint4(ohl[0], ohl[1], ohl[2], ohl[3]);
        *(uint4*)(g_hlo[dst] + hoff + 8) = make_uint4(ohl[4], ohl[5], ohl[6], ohl[7]);
        *(uint4*)(g_rhi + hoff)          = make_uint4(orh[0], orh[1], orh[2], orh[3]);
        *(uint4*)(g_rhi + hoff + 8)      = make_uint4(orh[4], orh[5], orh[6], orh[7]);
        *(uint4*)(g_rlo + hoff)          = make_uint4(orl[0], orl[1], orl[2], orl[3]);
        *(uint4*)(g_rlo + hoff + 8)      = make_uint4(orl[4], orl[5], orl[6], orl[7]);
    }
}

// ---------------- output projection ----------------
// grid (8, 32): bx = 128-col tile, by = 128-row batch tile
__global__ __launch_bounds__(256, 1)
void out_mma(const float* __restrict__ bout, float* __restrict__ out) {
    extern __shared__ char smem[];
    uint32_t sb = smem_u32(smem);
    int tid = threadIdx.x;
    int lane = tid & 31, wid = tid >> 5;
    int wm = wid >> 2, wn = wid & 3;
    int rowbase = blockIdx.y * 128;
    int colbase = blockIdx.x * 128;

    int r = tid >> 1;
    int cp0 = (tid & 1) * 4;
    size_t aoff = (size_t)(rowbase + r) * HID;
    size_t boff = (size_t)(colbase + r) * HID;

    float acc[4][4][4];
#pragma unroll
    for (int a = 0; a < 4; ++a)
#pragma unroll
        for (int b = 0; b < 4; ++b)
#pragma unroll
            for (int c = 0; c < 4; ++c) acc[a][b][c] = 0.0f;

#pragma unroll
    for (int s = 0; s < 2; ++s) {
        int k0 = s * BK;
        uint32_t st = sb + s * ST_SZ;
#pragma unroll
        for (int i = 0; i < 4; ++i) {
            int c = cp0 + i;
            uint32_t so = (uint32_t)(r * 128 + ((c ^ (r & 7)) << 4));
            cp16(st + ST_AHI + so, g_rhi + aoff + k0 + c * 8);
            cp16(st + ST_ALO + so, g_rlo + aoff + k0 + c * 8);
            cp16(st + ST_BHI + so, g_WOhi + boff + k0 + c * 8);
            cp16(st + ST_BLO + so, g_WOlo + boff + k0 + c * 8);
        }
        CP_COMMIT();
    }

    int a_row = wm * 64 + (lane & 15);
    int a_chi = lane >> 4;
    int b_row = wn * 32 + (lane & 7);
    int b_chi = (lane >> 3) & 1;

    for (int cc = 0; cc < NCH; ++cc) {
        int s = cc & 1;
        if (cc == NCH - 1) CP_WAIT0(); else CP_WAIT1();
        __syncthreads();
        uint32_t st = sb + s * ST_SZ;

#pragma unroll
        for (int kk = 0; kk < 4; ++kk) {
            uint32_t Ah[4][4], Al[4][4];
#pragma unroll
            for (int mf = 0; mf < 4; ++mf) {
                int row = a_row + mf * 16;
                uint32_t so = (uint32_t)(row * 128 + (((2 * kk + a_chi) ^ (row & 7)) << 4));
                LDSM4(Ah[mf], st + ST_AHI + so);
                LDSM4(Al[mf], st + ST_ALO + so);
            }
#pragma unroll
            for (int nf = 0; nf < 4; ++nf) {
                int row = b_row + nf * 8;
                uint32_t so = (uint32_t)(row * 128 + (((2 * kk + b_chi) ^ (row & 7)) << 4));
                uint32_t bh0, bh1, bl0, bl1;
                LDSM2(bh0, bh1, st + ST_BHI + so);
                LDSM2(bl0, bl1, st + ST_BLO + so);
#pragma unroll
                for (int mf = 0; mf < 4; ++mf) {
                    MMA(acc[mf][nf], Ah[mf], bh0, bh1);
                    MMA(acc[mf][nf], Ah[mf], bl0, bl1);
                    MMA(acc[mf][nf], Al[mf], bh0, bh1);
                }
            }
        }
        __syncthreads();
        if (cc + 2 < NCH) {
            int k0 = (cc + 2) * BK;
            uint32_t st2 = sb + s * ST_SZ;
#pragma unroll
            for (int i = 0; i < 4; ++i) {
                int c = cp0 + i;
                uint32_t so = (uint32_t)(r * 128 + ((c ^ (r & 7)) << 4));
                cp16(st2 + ST_AHI + so, g_rhi + aoff + k0 + c * 8);
                cp16(st2 + ST_ALO + so, g_rlo + aoff + k0 + c * 8);
                cp16(st2 + ST_BHI + so, g_WOhi + boff + k0 + c * 8);
                cp16(st2 + ST_BLO + so, g_WOlo + boff + k0 + c * 8);
            }
            CP_COMMIT();
        } else {
            CP_COMMIT();
        }
    }

    // ---- bias epilogue, direct from fragments ----
#pragma unroll
    for (int mf = 0; mf < 4; ++mf)
#pragma unroll
        for (int nf = 0; nf < 4; ++nf) {
            int m = rowbase + wm * 64 + mf * 16 + (lane >> 2);
            int n = colbase + wn * 32 + nf * 8 + (lane & 3) * 2;
            float b0 = bout[n], b1 = bout[n + 1];
            float2 v0 = make_float2(acc[mf][nf][0] + b0, acc[mf][nf][1] + b1);
            float2 v1 = make_float2(acc[mf][nf][2] + b0, acc[mf][nf][3] + b1);
            *(float2*)(out + (size_t)m * 1024 + n)       = v0;
            *(float2*)(out + (size_t)(m + 8) * 1024 + n) = v1;
        }
}

// ---------------- launch ----------------
extern "C" void kernel_launch(void* const* d_in, const int* in_sizes, int n_in,
                              void* d_out, int out_size) {
    const float* hidden = (const float*)d_in[0];  // (1, 4096, 1024)
    const float* W_ih   = (const float*)d_in[1];  // (3072, 1024)
    const float* W_hh   = (const float*)d_in[2];  // (3072, 1024)
    const float* b_ih   = (const float*)d_in[3];
    const float* b_hh   = (const float*)d_in[4];
    const float* W_out  = (const float*)d_in[5];  // (1024, 1024)
    const float* b_out  = (const float*)d_in[6];
    float* out = (float*)d_out;                    // (16, 4096, 1024)

    cudaFuncSetAttribute(gate_mma, cudaFuncAttributeMaxDynamicSharedMemorySize, SMEM_TOTAL);
    cudaFuncSetAttribute(out_mma,  cudaFuncAttributeMaxDynamicSharedMemorySize, SMEM_TOTAL);

    prep_fold<<<(4 * HID * HID) / 256, 256>>>(W_ih, W_hh, b_ih, b_hh);
    prep_wout<<<(HID * HID) / 256, 256>>>(W_out);
    prep_h<<<(BATCH * HID) / 256, 256>>>(hidden);

    dim3 ggrid(32, 32);
    dim3 ogrid(8, 32);

    for (int t = 0; t < STEPS; ++t) {
        int wsel = (t == 0) ? 1 : 0;
        int src = t & 1;
        int dst = (t + 1) & 1;
        gate_mma<<<ggrid, 256, SMEM_TOTAL>>>(wsel, src, dst);
        out_mma<<<ogrid, 256, SMEM_TOTAL>>>(b_out, out + (size_t)t * BATCH * 1024);
    }
}